// round 15
// baseline (speedup 1.0000x reference)
#include <cuda_runtime.h>
#include <math.h>

#define C_DIM 1024
#define NQ 10            // gated queries (ref has NQ+1 = 11 query rows)
#define NP 5             // q-pairs
#define MAXN 100000
#define K1_RPW 4         // rows per warp per tile
#define K1_WARPS 8
#define K1_RPB (K1_RPW * K1_WARPS)   // 32 rows per tile
#define K1_GRID 296                  // persistent, 2 CTAs/SM (16 warps)
#define K2_TILE 128
#define K2_GRID 592                  // persistent, 4 CTAs/SM

typedef unsigned long long u64;

// ---- scratch (static device memory; no allocations) ----
__device__ u64   g_Qp[NP * C_DIM];                    // packed q-pair diffs [p][c]
__device__ float g_inv[NQ + 1];                       // 1/||Q_q||
__device__ float g_logits[(size_t)NQ * MAXN];         // [q][n], 4 MB
__device__ float g_bmax[(size_t)K1_GRID * NQ];        // per-block max partials
__device__ float g_M[NQ];                             // per-q max logit
__device__ float g_Z[NQ];                             // per-q softmax denom
__device__ float g_partial[(size_t)K2_GRID * C_DIM];  // pass-2 partials
__device__ float g_pooled[C_DIM];

// ---- packed f32x2 helpers ----
__device__ __forceinline__ u64 f2fma(u64 a, u64 b, u64 c) {
    u64 d;
    asm("fma.rn.f32x2 %0, %1, %2, %3;" : "=l"(d) : "l"(a), "l"(b), "l"(c));
    return d;
}
__device__ __forceinline__ u64 f2add(u64 a, u64 b) {
    u64 d;
    asm("add.rn.f32x2 %0, %1, %2;" : "=l"(d) : "l"(a), "l"(b));
    return d;
}
__device__ __forceinline__ u64 fdup(float x) {
    u64 d;
    asm("mov.b64 %0, {%1, %1};" : "=l"(d) : "f"(x));
    return d;
}
__device__ __forceinline__ u64 fpack(float lo, float hi) {
    u64 d;
    asm("mov.b64 %0, {%1, %2};" : "=l"(d) : "f"(lo), "f"(hi));
    return d;
}
__device__ __forceinline__ float f2lo(u64 v) { return __uint_as_float((unsigned)v); }
__device__ __forceinline__ float f2hi(u64 v) { return __uint_as_float((unsigned)(v >> 32)); }
__device__ __forceinline__ float f2sum(u64 v) { return f2lo(v) + f2hi(v); }
__device__ __forceinline__ u64 shfl_xor64(u64 v, int off) {
    unsigned lo = (unsigned)v, hi = (unsigned)(v >> 32);
    lo = __shfl_xor_sync(0xffffffffu, lo, off);
    hi = __shfl_xor_sync(0xffffffffu, hi, off);
    return (u64)lo | ((u64)hi << 32);
}

// ============================================================
// K0a: per-q inverse norm (block per query row) + init Z/pooled
// ============================================================
__global__ void k0a_norms(const float* __restrict__ Q) {
    int q = blockIdx.x;
    int t = threadIdx.x;
    __shared__ float s_red[128];
    float ss = 0.f;
    for (int c = t; c < C_DIM; c += 128) {
        float v = Q[q * C_DIM + c];
        ss = fmaf(v, v, ss);
    }
    s_red[t] = ss;
    __syncthreads();
    for (int s = 64; s > 0; s >>= 1) {
        if (t < s) s_red[t] += s_red[t + s];
        __syncthreads();
    }
    if (t == 0) g_inv[q] = 1.0f / fmaxf(sqrtf(s_red[0]), 1e-12f);
    if (q == 0) {
        if (t < NQ) g_Z[t] = 0.f;
        for (int c = t; c < C_DIM; c += 128) g_pooled[c] = 0.f;
    }
}

// ============================================================
// K0b: build packed Qp pairs (8 blocks x 128 threads)
// ============================================================
__global__ void k0b_qp(const float* __restrict__ Q) {
    int c = blockIdx.x * 128 + threadIdx.x;
    if (c >= C_DIM) return;
    float ql = Q[NQ * C_DIM + c] * g_inv[NQ];
#pragma unroll
    for (int p = 0; p < NP; p++) {
        float lo = Q[(2 * p) * C_DIM + c] * g_inv[2 * p] - ql;
        float hi = Q[(2 * p + 1) * C_DIM + c] * g_inv[2 * p + 1] - ql;
        g_Qp[p * C_DIM + c] = fpack(lo, hi);
    }
}

// ============================================================
// K1: logits[q][n] = 100 * (Qd[q] . X[n]) / max(||X[n]||, eps)
// (R11 proven) balanced tile ranges, RPW=4 q-pair acc, 2 CTAs/SM,
// cross-tile prefetch, pair-merge reduction.
// ============================================================
__global__ __launch_bounds__(256, 2) void k1_logits(const float* __restrict__ X,
                                                    int N, int ntiles) {
    __shared__ u64 s_qp[NP * C_DIM];            // 40 KB
    __shared__ float s_wmax[K1_WARPS][NQ];
    int t = threadIdx.x;
    int warp = t >> 5, lane = t & 31;
    for (int i = t; i < NP * C_DIM; i += 256) s_qp[i] = g_Qp[i];
    if (t < K1_WARPS * NQ) ((float*)s_wmax)[t] = -1e30f;
    __syncthreads();

    bool hi16 = (lane & 16) != 0;

    int tb0 = (int)((long long)blockIdx.x * ntiles / gridDim.x);
    int tb1 = (int)((long long)(blockIdx.x + 1) * ntiles / gridDim.x);

    int ro[K1_RPW], ro_next[K1_RPW];
    {
        int row0 = tb0 * K1_RPB + warp * K1_RPW;
#pragma unroll
        for (int j = 0; j < K1_RPW; j++) {
            int r = row0 + j;
            if (r > N - 1) r = N - 1;
            ro[j] = r * C_DIM + 2 * lane;
        }
    }

    u64 A0[K1_RPW], A1[K1_RPW], B0[K1_RPW], B1[K1_RPW];
#pragma unroll
    for (int j = 0; j < K1_RPW; j++) {
        A0[j] = __ldcs((const u64*)(X + ro[j]));
        A1[j] = __ldcs((const u64*)(X + ro[j] + 64));
    }
#pragma unroll
    for (int j = 0; j < K1_RPW; j++) {
        B0[j] = __ldcs((const u64*)(X + ro[j] + 128));
        B1[j] = __ldcs((const u64*)(X + ro[j] + 192));
    }

    for (int tile = tb0; tile < tb1; tile++) {
        int row0 = tile * K1_RPB + warp * K1_RPW;
        {
            int row0n = (tile + 1) * K1_RPB + warp * K1_RPW;
#pragma unroll
            for (int j = 0; j < K1_RPW; j++) {
                int r = row0n + j;
                if (r > N - 1) r = N - 1;
                ro_next[j] = r * C_DIM + 2 * lane;
            }
        }

        u64 acc[K1_RPW][NP];
        u64 nacc[K1_RPW];
#pragma unroll
        for (int j = 0; j < K1_RPW; j++) {
            nacc[j] = 0ull;
#pragma unroll
            for (int p = 0; p < NP; p++) acc[j][p] = 0ull;
        }

#pragma unroll
        for (int kk = 0; kk < 8; kk++) {
            u64* x0 = (kk & 1) ? B0 : A0;
            u64* x1 = (kk & 1) ? B1 : A1;
            int cb = kk * 128 + 2 * lane;

            {
                u64 xd[2 * K1_RPW];
#pragma unroll
                for (int j = 0; j < K1_RPW; j++) {
                    u64 x = x0[j];
                    xd[2 * j] = fdup(f2lo(x));
                    xd[2 * j + 1] = fdup(f2hi(x));
                    nacc[j] = f2fma(x, x, nacc[j]);
                }
                if (kk < 6) {
                    int nb = (kk + 2) * 128;
#pragma unroll
                    for (int j = 0; j < K1_RPW; j++)
                        x0[j] = __ldcs((const u64*)(X + ro[j] + nb));
                } else {
                    int nb = (kk - 6) * 128;
#pragma unroll
                    for (int j = 0; j < K1_RPW; j++)
                        x0[j] = __ldcs((const u64*)(X + ro_next[j] + nb));
                }
#pragma unroll
                for (int p = 0; p < NP; p++) {
                    ulonglong2 qa = *(const ulonglong2*)&s_qp[p * C_DIM + cb];
#pragma unroll
                    for (int j = 0; j < K1_RPW; j++) {
                        acc[j][p] = f2fma(xd[2 * j], qa.x, acc[j][p]);
                        acc[j][p] = f2fma(xd[2 * j + 1], qa.y, acc[j][p]);
                    }
                }
            }
            {
                u64 xd[2 * K1_RPW];
#pragma unroll
                for (int j = 0; j < K1_RPW; j++) {
                    u64 x = x1[j];
                    xd[2 * j] = fdup(f2lo(x));
                    xd[2 * j + 1] = fdup(f2hi(x));
                    nacc[j] = f2fma(x, x, nacc[j]);
                }
                if (kk < 6) {
                    int nb = (kk + 2) * 128;
#pragma unroll
                    for (int j = 0; j < K1_RPW; j++)
                        x1[j] = __ldcs((const u64*)(X + ro[j] + nb + 64));
                } else {
                    int nb = (kk - 6) * 128;
#pragma unroll
                    for (int j = 0; j < K1_RPW; j++)
                        x1[j] = __ldcs((const u64*)(X + ro_next[j] + nb + 64));
                }
#pragma unroll
                for (int p = 0; p < NP; p++) {
                    ulonglong2 qb = *(const ulonglong2*)&s_qp[p * C_DIM + cb + 64];
#pragma unroll
                    for (int j = 0; j < K1_RPW; j++) {
                        acc[j][p] = f2fma(xd[2 * j], qb.x, acc[j][p]);
                        acc[j][p] = f2fma(xd[2 * j + 1], qb.y, acc[j][p]);
                    }
                }
            }
        }

        u64 nmA = fpack(f2sum(nacc[0]), f2sum(nacc[2]));
        u64 nmB = fpack(f2sum(nacc[1]), f2sum(nacc[3]));

        u64 A[NP], Bv[NP];
#pragma unroll
        for (int p = 0; p < NP; p++) {
            u64 keepA = hi16 ? acc[1][p] : acc[0][p];
            u64 sendA = hi16 ? acc[0][p] : acc[1][p];
            A[p] = f2add(keepA, shfl_xor64(sendA, 16));
            u64 keepB = hi16 ? acc[3][p] : acc[2][p];
            u64 sendB = hi16 ? acc[2][p] : acc[3][p];
            Bv[p] = f2add(keepB, shfl_xor64(sendB, 16));
        }
        u64 keepN = hi16 ? nmB : nmA;
        u64 sendN = hi16 ? nmA : nmB;
        u64 nm = f2add(keepN, shfl_xor64(sendN, 16));

#pragma unroll
        for (int off = 8; off; off >>= 1) {
            nm = f2add(nm, shfl_xor64(nm, off));
#pragma unroll
            for (int p = 0; p < NP; p++) {
                A[p] = f2add(A[p], shfl_xor64(A[p], off));
                Bv[p] = f2add(Bv[p], shfl_xor64(Bv[p], off));
            }
        }

        int rA = row0 + (hi16 ? 1 : 0);
        int rB = rA + 2;
        float scA = 100.0f / fmaxf(sqrtf(f2lo(nm)), 1e-12f);
        float scB = 100.0f / fmaxf(sqrtf(f2hi(nm)), 1e-12f);
        bool vA = (rA < N), vB = (rB < N);
        bool storer = (lane == 0) || (lane == 16);
#pragma unroll
        for (int p = 0; p < NP; p++) {
            float a0 = f2lo(A[p]) * scA, a1 = f2hi(A[p]) * scA;
            float b0 = f2lo(Bv[p]) * scB, b1 = f2hi(Bv[p]) * scB;
            if (storer && vA) {
                g_logits[(size_t)(2 * p) * N + rA] = a0;
                g_logits[(size_t)(2 * p + 1) * N + rA] = a1;
            }
            if (storer && vB) {
                g_logits[(size_t)(2 * p) * N + rB] = b0;
                g_logits[(size_t)(2 * p + 1) * N + rB] = b1;
            }
            float m0 = fmaxf(vA ? a0 : -1e30f, vB ? b0 : -1e30f);
            float m1 = fmaxf(vA ? a1 : -1e30f, vB ? b1 : -1e30f);
            m0 = fmaxf(m0, __shfl_xor_sync(0xffffffffu, m0, 16));
            m1 = fmaxf(m1, __shfl_xor_sync(0xffffffffu, m1, 16));
            if (lane == 0) {
                s_wmax[warp][2 * p] = fmaxf(s_wmax[warp][2 * p], m0);
                s_wmax[warp][2 * p + 1] = fmaxf(s_wmax[warp][2 * p + 1], m1);
            }
        }

#pragma unroll
        for (int j = 0; j < K1_RPW; j++) ro[j] = ro_next[j];
    }

    __syncthreads();
    if (t < NQ) {
        float m = -1e30f;
#pragma unroll
        for (int w = 0; w < K1_WARPS; w++) m = fmaxf(m, s_wmax[w][t]);
        g_bmax[(size_t)blockIdx.x * NQ + t] = m;
    }
}

// ============================================================
// K1.5b: Z[q] = sum_n exp(l - M); M merged from g_bmax in-kernel
// (grid = NQ*64 blocks; part 0 publishes g_M[q])
// ============================================================
__global__ void k15b_z(int N, int nbmax) {
    int q = blockIdx.x >> 6, part = blockIdx.x & 63;
    int t = threadIdx.x;
    __shared__ float red[256];

    float m = -1e30f;
    for (int b = t; b < nbmax; b += 256)
        m = fmaxf(m, g_bmax[(size_t)b * NQ + q]);
    red[t] = m;
    __syncthreads();
    for (int s = 128; s > 0; s >>= 1) {
        if (t < s) red[t] = fmaxf(red[t], red[t + s]);
        __syncthreads();
    }
    float M = red[0];
    if (part == 0 && t == 0) g_M[q] = M;
    __syncthreads();

    const float* l = g_logits + (size_t)q * N;
    float s = 0.f;
    int n4 = N >> 2;
    int stride = 64 * 256;
    for (int i = part * 256 + t; i < n4; i += stride) {
        float4 v = *(const float4*)(l + 4 * i);
        s += __expf(v.x - M) + __expf(v.y - M) + __expf(v.z - M) + __expf(v.w - M);
    }
    for (int n = 4 * n4 + part * 256 + t; n < N; n += stride)
        s += __expf(l[n] - M);
    red[t] = s;
    __syncthreads();
    for (int st = 128; st > 0; st >>= 1) {
        if (t < st) red[t] += red[t + st];
        __syncthreads();
    }
    if (t == 0) atomicAdd(&g_Z[q], red[0]);
}

// ============================================================
// K2: balanced contiguous row range per block; chunked s_g gather
// ============================================================
__global__ __launch_bounds__(256) void k2_wsum(const float* __restrict__ X, int N) {
    __shared__ float s_g[K2_TILE];
    __shared__ float s_m[NQ], s_iz[NQ];
    int t = threadIdx.x;
    if (t < NQ) { s_m[t] = g_M[t]; s_iz[t] = (1.0f / NQ) / g_Z[t]; }
    __syncthreads();

    int r0 = (int)((long long)blockIdx.x * N / gridDim.x);
    int r1 = (int)((long long)(blockIdx.x + 1) * N / gridDim.x);

    float4 a = make_float4(0.f, 0.f, 0.f, 0.f);

    for (int n0 = r0; n0 < r1; n0 += K2_TILE) {
        int nv = min(K2_TILE, r1 - n0);
        __syncthreads();
        if (t < nv) {
            int n = n0 + t;
            float gs = 0.f;
#pragma unroll
            for (int q = 0; q < NQ; q++)
                gs = fmaf(__expf(g_logits[(size_t)q * N + n] - s_m[q]), s_iz[q], gs);
            s_g[t] = gs;
        }
        __syncthreads();

        const float* xb = X + (size_t)n0 * C_DIM + 4 * t;
        int r = 0;
        for (; r + 8 <= nv; r += 8) {
            float4 x[8];
#pragma unroll
            for (int i = 0; i < 8; i++)
                x[i] = __ldcs((const float4*)(xb + (size_t)(r + i) * C_DIM));
#pragma unroll
            for (int i = 0; i < 8; i++) {
                float g = s_g[r + i];
                a.x = fmaf(g, x[i].x, a.x); a.y = fmaf(g, x[i].y, a.y);
                a.z = fmaf(g, x[i].z, a.z); a.w = fmaf(g, x[i].w, a.w);
            }
        }
        for (; r < nv; r++) {
            float4 x = __ldcs((const float4*)(xb + (size_t)r * C_DIM));
            float g = s_g[r];
            a.x = fmaf(g, x.x, a.x); a.y = fmaf(g, x.y, a.y);
            a.z = fmaf(g, x.z, a.z); a.w = fmaf(g, x.w, a.w);
        }
    }
    *(float4*)(g_partial + (size_t)blockIdx.x * C_DIM + 4 * t) = a;
}

// ============================================================
// K2.5: pooled[c] = sum_b partial[b][c]  (grid 512 = 8 cpart x 64 bpart)
// ============================================================
__global__ void k25_reduce(int nblocks) {
    int cpart = blockIdx.x & 7;
    int bpart = blockIdx.x >> 3;
    int c = cpart * 128 + threadIdx.x;
    float s = 0.f;
    for (int bb = bpart; bb < nblocks; bb += 64)
        s += g_partial[(size_t)bb * C_DIM + c];
    atomicAdd(&g_pooled[c], s);
}

// ============================================================
// K3: out[j] = b[j] + sum_c pooled[c]*W[j][c]   (grid 128 x 256)
// ============================================================
__global__ __launch_bounds__(256) void k3_linear(const float* __restrict__ W,
                                                 const float* __restrict__ bias,
                                                 float* __restrict__ out) {
    int t = threadIdx.x;
    int j0 = blockIdx.x * 8;
    float4 p = *(const float4*)(g_pooled + 4 * t);
    float part[8];
#pragma unroll
    for (int j = 0; j < 8; j++) {
        const float4 w = *(const float4*)(W + (size_t)(j0 + j) * C_DIM + 4 * t);
        part[j] = fmaf(p.x, w.x, fmaf(p.y, w.y, fmaf(p.z, w.z, p.w * w.w)));
    }
#pragma unroll
    for (int j = 0; j < 8; j++)
#pragma unroll
        for (int off = 16; off; off >>= 1)
            part[j] += __shfl_xor_sync(0xffffffffu, part[j], off);
    __shared__ float s_p[8][8];
    int warp = t >> 5, lane = t & 31;
    if (lane == 0)
#pragma unroll
        for (int j = 0; j < 8; j++) s_p[warp][j] = part[j];
    __syncthreads();
    if (t < 8) {
        float s = 0.f;
#pragma unroll
        for (int w = 0; w < 8; w++) s += s_p[w][t];
        out[j0 + t] = s + bias[j0 + t];
    }
}

// ============================================================
extern "C" void kernel_launch(void* const* d_in, const int* in_sizes, int n_in,
                              void* d_out, int out_size) {
    const float* X = (const float*)d_in[0];
    const float* Q = (const float*)d_in[1];
    const float* W = (const float*)d_in[2];
    const float* b = (const float*)d_in[3];
    float* out = (float*)d_out;

    int N = in_sizes[0] / C_DIM;
    if (N > MAXN) N = MAXN;

    int k1_tiles = (N + K1_RPB - 1) / K1_RPB;
    int k1_grid = (K1_GRID < k1_tiles) ? K1_GRID : k1_tiles;
    int k2_grid = (K2_GRID < N) ? K2_GRID : N;

    k0a_norms<<<NQ + 1, 128>>>(Q);
    k0b_qp<<<8, 128>>>(Q);
    k1_logits<<<k1_grid, 256>>>(X, N, k1_tiles);
    k15b_z<<<NQ * 64, 256>>>(N, k1_grid);
    k2_wsum<<<k2_grid, 256>>>(X, N);
    k25_reduce<<<512, 128>>>(k2_grid);
    k3_linear<<<128, 256>>>(W, b, out);
}

// round 16
// speedup vs baseline: 1.1686x; 1.1686x over previous
#include <cuda_runtime.h>
#include <math.h>

#define C_DIM 1024
#define NQ 10            // gated queries (ref has NQ+1 = 11 query rows)
#define NP 5             // q-pairs
#define MAXN 100000
#define K1_RPW 4         // rows per warp per tile
#define K1_WARPS 8
#define K1_RPB (K1_RPW * K1_WARPS)   // 32 rows per tile
#define K1_GRID 296                  // persistent, 2 CTAs/SM (16 warps)
#define K2_TILE 128
#define K2_GRID 592                  // persistent, 4 CTAs/SM

typedef unsigned long long u64;

// ---- scratch (static device memory; no allocations) ----
__device__ u64   g_Qp[NP * C_DIM];                    // packed q-pair diffs [p][c]
__device__ float g_inv[NQ + 1];                       // 1/||Q_q||
__device__ float g_logits[(size_t)NQ * MAXN];         // [q][n], 4 MB
__device__ float g_bmax[(size_t)K1_GRID * NQ];        // per-block max partials
__device__ float g_M[NQ];                             // per-q max logit
__device__ float g_Z[NQ];                             // per-q softmax denom
__device__ float g_pooled[C_DIM];

// ---- packed f32x2 helpers ----
__device__ __forceinline__ u64 f2fma(u64 a, u64 b, u64 c) {
    u64 d;
    asm("fma.rn.f32x2 %0, %1, %2, %3;" : "=l"(d) : "l"(a), "l"(b), "l"(c));
    return d;
}
__device__ __forceinline__ u64 f2add(u64 a, u64 b) {
    u64 d;
    asm("add.rn.f32x2 %0, %1, %2;" : "=l"(d) : "l"(a), "l"(b));
    return d;
}
__device__ __forceinline__ u64 fdup(float x) {
    u64 d;
    asm("mov.b64 %0, {%1, %1};" : "=l"(d) : "f"(x));
    return d;
}
__device__ __forceinline__ u64 fpack(float lo, float hi) {
    u64 d;
    asm("mov.b64 %0, {%1, %2};" : "=l"(d) : "f"(lo), "f"(hi));
    return d;
}
__device__ __forceinline__ float f2lo(u64 v) { return __uint_as_float((unsigned)v); }
__device__ __forceinline__ float f2hi(u64 v) { return __uint_as_float((unsigned)(v >> 32)); }
__device__ __forceinline__ float f2sum(u64 v) { return f2lo(v) + f2hi(v); }
__device__ __forceinline__ u64 shfl_xor64(u64 v, int off) {
    unsigned lo = (unsigned)v, hi = (unsigned)(v >> 32);
    lo = __shfl_xor_sync(0xffffffffu, lo, off);
    hi = __shfl_xor_sync(0xffffffffu, hi, off);
    return (u64)lo | ((u64)hi << 32);
}

// ============================================================
// K0a: per-q inverse norm (block per query row) + init Z/pooled
// ============================================================
__global__ void k0a_norms(const float* __restrict__ Q) {
    int q = blockIdx.x;
    int t = threadIdx.x;
    __shared__ float s_red[128];
    float ss = 0.f;
    for (int c = t; c < C_DIM; c += 128) {
        float v = Q[q * C_DIM + c];
        ss = fmaf(v, v, ss);
    }
    s_red[t] = ss;
    __syncthreads();
    for (int s = 64; s > 0; s >>= 1) {
        if (t < s) s_red[t] += s_red[t + s];
        __syncthreads();
    }
    if (t == 0) g_inv[q] = 1.0f / fmaxf(sqrtf(s_red[0]), 1e-12f);
    if (q == 0) {
        if (t < NQ) g_Z[t] = 0.f;
        for (int c = t; c < C_DIM; c += 128) g_pooled[c] = 0.f;
    }
}

// ============================================================
// K0b: build packed Qp pairs (8 blocks x 128 threads)
// ============================================================
__global__ void k0b_qp(const float* __restrict__ Q) {
    int c = blockIdx.x * 128 + threadIdx.x;
    if (c >= C_DIM) return;
    float ql = Q[NQ * C_DIM + c] * g_inv[NQ];
#pragma unroll
    for (int p = 0; p < NP; p++) {
        float lo = Q[(2 * p) * C_DIM + c] * g_inv[2 * p] - ql;
        float hi = Q[(2 * p + 1) * C_DIM + c] * g_inv[2 * p + 1] - ql;
        g_Qp[p * C_DIM + c] = fpack(lo, hi);
    }
}

// ============================================================
// K1: logits[q][n] = 100 * (Qd[q] . X[n]) / max(||X[n]||, eps)
// (R11 proven) balanced tile ranges, RPW=4 q-pair acc, 2 CTAs/SM,
// cross-tile prefetch, pair-merge reduction.
// ============================================================
__global__ __launch_bounds__(256, 2) void k1_logits(const float* __restrict__ X,
                                                    int N, int ntiles) {
    __shared__ u64 s_qp[NP * C_DIM];            // 40 KB
    __shared__ float s_wmax[K1_WARPS][NQ];
    int t = threadIdx.x;
    int warp = t >> 5, lane = t & 31;
    for (int i = t; i < NP * C_DIM; i += 256) s_qp[i] = g_Qp[i];
    if (t < K1_WARPS * NQ) ((float*)s_wmax)[t] = -1e30f;
    __syncthreads();

    bool hi16 = (lane & 16) != 0;

    int tb0 = (int)((long long)blockIdx.x * ntiles / gridDim.x);
    int tb1 = (int)((long long)(blockIdx.x + 1) * ntiles / gridDim.x);

    int ro[K1_RPW], ro_next[K1_RPW];
    {
        int row0 = tb0 * K1_RPB + warp * K1_RPW;
#pragma unroll
        for (int j = 0; j < K1_RPW; j++) {
            int r = row0 + j;
            if (r > N - 1) r = N - 1;
            ro[j] = r * C_DIM + 2 * lane;
        }
    }

    u64 A0[K1_RPW], A1[K1_RPW], B0[K1_RPW], B1[K1_RPW];
#pragma unroll
    for (int j = 0; j < K1_RPW; j++) {
        A0[j] = __ldcs((const u64*)(X + ro[j]));
        A1[j] = __ldcs((const u64*)(X + ro[j] + 64));
    }
#pragma unroll
    for (int j = 0; j < K1_RPW; j++) {
        B0[j] = __ldcs((const u64*)(X + ro[j] + 128));
        B1[j] = __ldcs((const u64*)(X + ro[j] + 192));
    }

    for (int tile = tb0; tile < tb1; tile++) {
        int row0 = tile * K1_RPB + warp * K1_RPW;
        {
            int row0n = (tile + 1) * K1_RPB + warp * K1_RPW;
#pragma unroll
            for (int j = 0; j < K1_RPW; j++) {
                int r = row0n + j;
                if (r > N - 1) r = N - 1;
                ro_next[j] = r * C_DIM + 2 * lane;
            }
        }

        u64 acc[K1_RPW][NP];
        u64 nacc[K1_RPW];
#pragma unroll
        for (int j = 0; j < K1_RPW; j++) {
            nacc[j] = 0ull;
#pragma unroll
            for (int p = 0; p < NP; p++) acc[j][p] = 0ull;
        }

#pragma unroll
        for (int kk = 0; kk < 8; kk++) {
            u64* x0 = (kk & 1) ? B0 : A0;
            u64* x1 = (kk & 1) ? B1 : A1;
            int cb = kk * 128 + 2 * lane;

            {
                u64 xd[2 * K1_RPW];
#pragma unroll
                for (int j = 0; j < K1_RPW; j++) {
                    u64 x = x0[j];
                    xd[2 * j] = fdup(f2lo(x));
                    xd[2 * j + 1] = fdup(f2hi(x));
                    nacc[j] = f2fma(x, x, nacc[j]);
                }
                if (kk < 6) {
                    int nb = (kk + 2) * 128;
#pragma unroll
                    for (int j = 0; j < K1_RPW; j++)
                        x0[j] = __ldcs((const u64*)(X + ro[j] + nb));
                } else {
                    int nb = (kk - 6) * 128;
#pragma unroll
                    for (int j = 0; j < K1_RPW; j++)
                        x0[j] = __ldcs((const u64*)(X + ro_next[j] + nb));
                }
#pragma unroll
                for (int p = 0; p < NP; p++) {
                    ulonglong2 qa = *(const ulonglong2*)&s_qp[p * C_DIM + cb];
#pragma unroll
                    for (int j = 0; j < K1_RPW; j++) {
                        acc[j][p] = f2fma(xd[2 * j], qa.x, acc[j][p]);
                        acc[j][p] = f2fma(xd[2 * j + 1], qa.y, acc[j][p]);
                    }
                }
            }
            {
                u64 xd[2 * K1_RPW];
#pragma unroll
                for (int j = 0; j < K1_RPW; j++) {
                    u64 x = x1[j];
                    xd[2 * j] = fdup(f2lo(x));
                    xd[2 * j + 1] = fdup(f2hi(x));
                    nacc[j] = f2fma(x, x, nacc[j]);
                }
                if (kk < 6) {
                    int nb = (kk + 2) * 128;
#pragma unroll
                    for (int j = 0; j < K1_RPW; j++)
                        x1[j] = __ldcs((const u64*)(X + ro[j] + nb + 64));
                } else {
                    int nb = (kk - 6) * 128;
#pragma unroll
                    for (int j = 0; j < K1_RPW; j++)
                        x1[j] = __ldcs((const u64*)(X + ro_next[j] + nb + 64));
                }
#pragma unroll
                for (int p = 0; p < NP; p++) {
                    ulonglong2 qb = *(const ulonglong2*)&s_qp[p * C_DIM + cb + 64];
#pragma unroll
                    for (int j = 0; j < K1_RPW; j++) {
                        acc[j][p] = f2fma(xd[2 * j], qb.x, acc[j][p]);
                        acc[j][p] = f2fma(xd[2 * j + 1], qb.y, acc[j][p]);
                    }
                }
            }
        }

        u64 nmA = fpack(f2sum(nacc[0]), f2sum(nacc[2]));
        u64 nmB = fpack(f2sum(nacc[1]), f2sum(nacc[3]));

        u64 A[NP], Bv[NP];
#pragma unroll
        for (int p = 0; p < NP; p++) {
            u64 keepA = hi16 ? acc[1][p] : acc[0][p];
            u64 sendA = hi16 ? acc[0][p] : acc[1][p];
            A[p] = f2add(keepA, shfl_xor64(sendA, 16));
            u64 keepB = hi16 ? acc[3][p] : acc[2][p];
            u64 sendB = hi16 ? acc[2][p] : acc[3][p];
            Bv[p] = f2add(keepB, shfl_xor64(sendB, 16));
        }
        u64 keepN = hi16 ? nmB : nmA;
        u64 sendN = hi16 ? nmA : nmB;
        u64 nm = f2add(keepN, shfl_xor64(sendN, 16));

#pragma unroll
        for (int off = 8; off; off >>= 1) {
            nm = f2add(nm, shfl_xor64(nm, off));
#pragma unroll
            for (int p = 0; p < NP; p++) {
                A[p] = f2add(A[p], shfl_xor64(A[p], off));
                Bv[p] = f2add(Bv[p], shfl_xor64(Bv[p], off));
            }
        }

        int rA = row0 + (hi16 ? 1 : 0);
        int rB = rA + 2;
        float scA = 100.0f / fmaxf(sqrtf(f2lo(nm)), 1e-12f);
        float scB = 100.0f / fmaxf(sqrtf(f2hi(nm)), 1e-12f);
        bool vA = (rA < N), vB = (rB < N);
        bool storer = (lane == 0) || (lane == 16);
#pragma unroll
        for (int p = 0; p < NP; p++) {
            float a0 = f2lo(A[p]) * scA, a1 = f2hi(A[p]) * scA;
            float b0 = f2lo(Bv[p]) * scB, b1 = f2hi(Bv[p]) * scB;
            if (storer && vA) {
                g_logits[(size_t)(2 * p) * N + rA] = a0;
                g_logits[(size_t)(2 * p + 1) * N + rA] = a1;
            }
            if (storer && vB) {
                g_logits[(size_t)(2 * p) * N + rB] = b0;
                g_logits[(size_t)(2 * p + 1) * N + rB] = b1;
            }
            float m0 = fmaxf(vA ? a0 : -1e30f, vB ? b0 : -1e30f);
            float m1 = fmaxf(vA ? a1 : -1e30f, vB ? b1 : -1e30f);
            m0 = fmaxf(m0, __shfl_xor_sync(0xffffffffu, m0, 16));
            m1 = fmaxf(m1, __shfl_xor_sync(0xffffffffu, m1, 16));
            if (lane == 0) {
                s_wmax[warp][2 * p] = fmaxf(s_wmax[warp][2 * p], m0);
                s_wmax[warp][2 * p + 1] = fmaxf(s_wmax[warp][2 * p + 1], m1);
            }
        }

#pragma unroll
        for (int j = 0; j < K1_RPW; j++) ro[j] = ro_next[j];
    }

    __syncthreads();
    if (t < NQ) {
        float m = -1e30f;
#pragma unroll
        for (int w = 0; w < K1_WARPS; w++) m = fmaxf(m, s_wmax[w][t]);
        g_bmax[(size_t)blockIdx.x * NQ + t] = m;
    }
}

// ============================================================
// K1.5b: Z[q] = sum_n exp(l - M); M merged from g_bmax in-kernel
// (grid = NQ*64 blocks; part 0 publishes g_M[q])
// ============================================================
__global__ void k15b_z(int N, int nbmax) {
    int q = blockIdx.x >> 6, part = blockIdx.x & 63;
    int t = threadIdx.x;
    __shared__ float red[256];

    float m = -1e30f;
    for (int b = t; b < nbmax; b += 256)
        m = fmaxf(m, g_bmax[(size_t)b * NQ + q]);
    red[t] = m;
    __syncthreads();
    for (int s = 128; s > 0; s >>= 1) {
        if (t < s) red[t] = fmaxf(red[t], red[t + s]);
        __syncthreads();
    }
    float M = red[0];
    if (part == 0 && t == 0) g_M[q] = M;
    __syncthreads();

    const float* l = g_logits + (size_t)q * N;
    float s = 0.f;
    int n4 = N >> 2;
    int stride = 64 * 256;
    for (int i = part * 256 + t; i < n4; i += stride) {
        float4 v = *(const float4*)(l + 4 * i);
        s += __expf(v.x - M) + __expf(v.y - M) + __expf(v.z - M) + __expf(v.w - M);
    }
    for (int n = 4 * n4 + part * 256 + t; n < N; n += stride)
        s += __expf(l[n] - M);
    red[t] = s;
    __syncthreads();
    for (int st = 128; st > 0; st >>= 1) {
        if (t < st) red[t] += red[t + st];
        __syncthreads();
    }
    if (t == 0) atomicAdd(&g_Z[q], red[0]);
}

// ============================================================
// K2: balanced contiguous row range per block; chunked s_g gather;
// epilogue atomicAdds partials straight into g_pooled (no k25).
// ============================================================
__global__ __launch_bounds__(256) void k2_wsum(const float* __restrict__ X, int N) {
    __shared__ float s_g[K2_TILE];
    __shared__ float s_m[NQ], s_iz[NQ];
    int t = threadIdx.x;
    if (t < NQ) { s_m[t] = g_M[t]; s_iz[t] = (1.0f / NQ) / g_Z[t]; }
    __syncthreads();

    int r0 = (int)((long long)blockIdx.x * N / gridDim.x);
    int r1 = (int)((long long)(blockIdx.x + 1) * N / gridDim.x);

    float4 a = make_float4(0.f, 0.f, 0.f, 0.f);

    for (int n0 = r0; n0 < r1; n0 += K2_TILE) {
        int nv = min(K2_TILE, r1 - n0);
        __syncthreads();
        if (t < nv) {
            int n = n0 + t;
            float gs = 0.f;
#pragma unroll
            for (int q = 0; q < NQ; q++)
                gs = fmaf(__expf(g_logits[(size_t)q * N + n] - s_m[q]), s_iz[q], gs);
            s_g[t] = gs;
        }
        __syncthreads();

        const float* xb = X + (size_t)n0 * C_DIM + 4 * t;
        int r = 0;
        for (; r + 8 <= nv; r += 8) {
            float4 x[8];
#pragma unroll
            for (int i = 0; i < 8; i++)
                x[i] = __ldcs((const float4*)(xb + (size_t)(r + i) * C_DIM));
#pragma unroll
            for (int i = 0; i < 8; i++) {
                float g = s_g[r + i];
                a.x = fmaf(g, x[i].x, a.x); a.y = fmaf(g, x[i].y, a.y);
                a.z = fmaf(g, x[i].z, a.z); a.w = fmaf(g, x[i].w, a.w);
            }
        }
        for (; r < nv; r++) {
            float4 x = __ldcs((const float4*)(xb + (size_t)r * C_DIM));
            float g = s_g[r];
            a.x = fmaf(g, x.x, a.x); a.y = fmaf(g, x.y, a.y);
            a.z = fmaf(g, x.z, a.z); a.w = fmaf(g, x.w, a.w);
        }
    }
    atomicAdd(&g_pooled[4 * t + 0], a.x);
    atomicAdd(&g_pooled[4 * t + 1], a.y);
    atomicAdd(&g_pooled[4 * t + 2], a.z);
    atomicAdd(&g_pooled[4 * t + 3], a.w);
}

// ============================================================
// K3: out[j] = b[j] + sum_c pooled[c]*W[j][c]   (grid 128 x 256)
// ============================================================
__global__ __launch_bounds__(256) void k3_linear(const float* __restrict__ W,
                                                 const float* __restrict__ bias,
                                                 float* __restrict__ out) {
    int t = threadIdx.x;
    int j0 = blockIdx.x * 8;
    float4 p = *(const float4*)(g_pooled + 4 * t);
    float part[8];
#pragma unroll
    for (int j = 0; j < 8; j++) {
        const float4 w = *(const float4*)(W + (size_t)(j0 + j) * C_DIM + 4 * t);
        part[j] = fmaf(p.x, w.x, fmaf(p.y, w.y, fmaf(p.z, w.z, p.w * w.w)));
    }
#pragma unroll
    for (int j = 0; j < 8; j++)
#pragma unroll
        for (int off = 16; off; off >>= 1)
            part[j] += __shfl_xor_sync(0xffffffffu, part[j], off);
    __shared__ float s_p[8][8];
    int warp = t >> 5, lane = t & 31;
    if (lane == 0)
#pragma unroll
        for (int j = 0; j < 8; j++) s_p[warp][j] = part[j];
    __syncthreads();
    if (t < 8) {
        float s = 0.f;
#pragma unroll
        for (int w = 0; w < 8; w++) s += s_p[w][t];
        out[j0 + t] = s + bias[j0 + t];
    }
}

// ============================================================
extern "C" void kernel_launch(void* const* d_in, const int* in_sizes, int n_in,
                              void* d_out, int out_size) {
    const float* X = (const float*)d_in[0];
    const float* Q = (const float*)d_in[1];
    const float* W = (const float*)d_in[2];
    const float* b = (const float*)d_in[3];
    float* out = (float*)d_out;

    int N = in_sizes[0] / C_DIM;
    if (N > MAXN) N = MAXN;

    int k1_tiles = (N + K1_RPB - 1) / K1_RPB;
    int k1_grid = (K1_GRID < k1_tiles) ? K1_GRID : k1_tiles;
    int k2_grid = (K2_GRID < N) ? K2_GRID : N;

    k0a_norms<<<NQ + 1, 128>>>(Q);
    k0b_qp<<<8, 128>>>(Q);
    k1_logits<<<k1_grid, 256>>>(X, N, k1_tiles);
    k15b_z<<<NQ * 64, 256>>>(N, k1_grid);
    k2_wsum<<<k2_grid, 256>>>(X, N);
    k3_linear<<<128, 256>>>(W, b, out);
}

// round 17
// speedup vs baseline: 1.1953x; 1.0229x over previous
#include <cuda_runtime.h>
#include <math.h>

#define C_DIM 1024
#define NQ 10            // gated queries (ref has NQ+1 = 11 query rows)
#define NP 5             // q-pairs
#define MAXN 100000
#define K1_RPW 4         // rows per warp per tile
#define K1_WARPS 8
#define K1_RPB (K1_RPW * K1_WARPS)   // 32 rows per tile
#define K1_GRID 296                  // persistent, 2 CTAs/SM (16 warps)
#define K2_TILE 128
#define K2_GRID 592                  // persistent, 4 CTAs/SM

typedef unsigned long long u64;

// ---- scratch (static device memory; no allocations) ----
__device__ u64    g_Qp[NP * C_DIM];                   // packed q-pair diffs [p][c]
__device__ float  g_inv[NQ + 1];                      // 1/||Q_q||
__device__ float  g_logits[(size_t)NQ * MAXN];        // [q][n], 4 MB
__device__ float2 g_bmz[(size_t)K1_GRID * NQ];        // per-block (max, z) partials
__device__ float  g_M[NQ];                            // per-q max logit
__device__ float  g_Z[NQ];                            // per-q softmax denom
__device__ float  g_pooled[C_DIM];

// ---- packed f32x2 helpers ----
__device__ __forceinline__ u64 f2fma(u64 a, u64 b, u64 c) {
    u64 d;
    asm("fma.rn.f32x2 %0, %1, %2, %3;" : "=l"(d) : "l"(a), "l"(b), "l"(c));
    return d;
}
__device__ __forceinline__ u64 f2add(u64 a, u64 b) {
    u64 d;
    asm("add.rn.f32x2 %0, %1, %2;" : "=l"(d) : "l"(a), "l"(b));
    return d;
}
__device__ __forceinline__ u64 fdup(float x) {
    u64 d;
    asm("mov.b64 %0, {%1, %1};" : "=l"(d) : "f"(x));
    return d;
}
__device__ __forceinline__ u64 fpack(float lo, float hi) {
    u64 d;
    asm("mov.b64 %0, {%1, %2};" : "=l"(d) : "f"(lo), "f"(hi));
    return d;
}
__device__ __forceinline__ float f2lo(u64 v) { return __uint_as_float((unsigned)v); }
__device__ __forceinline__ float f2hi(u64 v) { return __uint_as_float((unsigned)(v >> 32)); }
__device__ __forceinline__ float f2sum(u64 v) { return f2lo(v) + f2hi(v); }
__device__ __forceinline__ u64 shfl_xor64(u64 v, int off) {
    unsigned lo = (unsigned)v, hi = (unsigned)(v >> 32);
    lo = __shfl_xor_sync(0xffffffffu, lo, off);
    hi = __shfl_xor_sync(0xffffffffu, hi, off);
    return (u64)lo | ((u64)hi << 32);
}

// ============================================================
// K0a: per-q inverse norm (block per query row) + init pooled
// ============================================================
__global__ void k0a_norms(const float* __restrict__ Q) {
    int q = blockIdx.x;
    int t = threadIdx.x;
    __shared__ float s_red[128];
    float ss = 0.f;
    for (int c = t; c < C_DIM; c += 128) {
        float v = Q[q * C_DIM + c];
        ss = fmaf(v, v, ss);
    }
    s_red[t] = ss;
    __syncthreads();
    for (int s = 64; s > 0; s >>= 1) {
        if (t < s) s_red[t] += s_red[t + s];
        __syncthreads();
    }
    if (t == 0) g_inv[q] = 1.0f / fmaxf(sqrtf(s_red[0]), 1e-12f);
    if (q == 0) {
        for (int c = t; c < C_DIM; c += 128) g_pooled[c] = 0.f;
    }
}

// ============================================================
// K0b: build packed Qp pairs (8 blocks x 128 threads)
// ============================================================
__global__ void k0b_qp(const float* __restrict__ Q) {
    int c = blockIdx.x * 128 + threadIdx.x;
    if (c >= C_DIM) return;
    float ql = Q[NQ * C_DIM + c] * g_inv[NQ];
#pragma unroll
    for (int p = 0; p < NP; p++) {
        float lo = Q[(2 * p) * C_DIM + c] * g_inv[2 * p] - ql;
        float hi = Q[(2 * p + 1) * C_DIM + c] * g_inv[2 * p + 1] - ql;
        g_Qp[p * C_DIM + c] = fpack(lo, hi);
    }
}

// ============================================================
// K1: logits + fused online softmax stats (m,z) per block.
// Balanced tile ranges, RPW=4 q-pair acc, 2 CTAs/SM,
// cross-tile prefetch, pair-merge reduction.
// ============================================================
__global__ __launch_bounds__(256, 2) void k1_logits(const float* __restrict__ X,
                                                    int N, int ntiles) {
    __shared__ u64 s_qp[NP * C_DIM];            // 40 KB
    __shared__ float2 s_mz[K1_WARPS][2][NQ];    // online (m,z) per warp/half/q
    int t = threadIdx.x;
    int warp = t >> 5, lane = t & 31;
    for (int i = t; i < NP * C_DIM; i += 256) s_qp[i] = g_Qp[i];
    if (t < K1_WARPS * 2 * NQ)
        ((float2*)s_mz)[t] = make_float2(-1e30f, 0.f);
    __syncthreads();

    bool hi16 = (lane & 16) != 0;
    int lq = lane & 15;                         // q owned by this lane (if < NQ)

    int tb0 = (int)((long long)blockIdx.x * ntiles / gridDim.x);
    int tb1 = (int)((long long)(blockIdx.x + 1) * ntiles / gridDim.x);

    int ro[K1_RPW], ro_next[K1_RPW];
    {
        int row0 = tb0 * K1_RPB + warp * K1_RPW;
#pragma unroll
        for (int j = 0; j < K1_RPW; j++) {
            int r = row0 + j;
            if (r > N - 1) r = N - 1;
            ro[j] = r * C_DIM + 2 * lane;
        }
    }

    u64 A0[K1_RPW], A1[K1_RPW], B0[K1_RPW], B1[K1_RPW];
#pragma unroll
    for (int j = 0; j < K1_RPW; j++) {
        A0[j] = __ldcs((const u64*)(X + ro[j]));
        A1[j] = __ldcs((const u64*)(X + ro[j] + 64));
    }
#pragma unroll
    for (int j = 0; j < K1_RPW; j++) {
        B0[j] = __ldcs((const u64*)(X + ro[j] + 128));
        B1[j] = __ldcs((const u64*)(X + ro[j] + 192));
    }

    for (int tile = tb0; tile < tb1; tile++) {
        int row0 = tile * K1_RPB + warp * K1_RPW;
        {
            int row0n = (tile + 1) * K1_RPB + warp * K1_RPW;
#pragma unroll
            for (int j = 0; j < K1_RPW; j++) {
                int r = row0n + j;
                if (r > N - 1) r = N - 1;
                ro_next[j] = r * C_DIM + 2 * lane;
            }
        }

        u64 acc[K1_RPW][NP];
        u64 nacc[K1_RPW];
#pragma unroll
        for (int j = 0; j < K1_RPW; j++) {
            nacc[j] = 0ull;
#pragma unroll
            for (int p = 0; p < NP; p++) acc[j][p] = 0ull;
        }

#pragma unroll
        for (int kk = 0; kk < 8; kk++) {
            u64* x0 = (kk & 1) ? B0 : A0;
            u64* x1 = (kk & 1) ? B1 : A1;
            int cb = kk * 128 + 2 * lane;

            {
                u64 xd[2 * K1_RPW];
#pragma unroll
                for (int j = 0; j < K1_RPW; j++) {
                    u64 x = x0[j];
                    xd[2 * j] = fdup(f2lo(x));
                    xd[2 * j + 1] = fdup(f2hi(x));
                    nacc[j] = f2fma(x, x, nacc[j]);
                }
                if (kk < 6) {
                    int nb = (kk + 2) * 128;
#pragma unroll
                    for (int j = 0; j < K1_RPW; j++)
                        x0[j] = __ldcs((const u64*)(X + ro[j] + nb));
                } else {
                    int nb = (kk - 6) * 128;
#pragma unroll
                    for (int j = 0; j < K1_RPW; j++)
                        x0[j] = __ldcs((const u64*)(X + ro_next[j] + nb));
                }
#pragma unroll
                for (int p = 0; p < NP; p++) {
                    ulonglong2 qa = *(const ulonglong2*)&s_qp[p * C_DIM + cb];
#pragma unroll
                    for (int j = 0; j < K1_RPW; j++) {
                        acc[j][p] = f2fma(xd[2 * j], qa.x, acc[j][p]);
                        acc[j][p] = f2fma(xd[2 * j + 1], qa.y, acc[j][p]);
                    }
                }
            }
            {
                u64 xd[2 * K1_RPW];
#pragma unroll
                for (int j = 0; j < K1_RPW; j++) {
                    u64 x = x1[j];
                    xd[2 * j] = fdup(f2lo(x));
                    xd[2 * j + 1] = fdup(f2hi(x));
                    nacc[j] = f2fma(x, x, nacc[j]);
                }
                if (kk < 6) {
                    int nb = (kk + 2) * 128;
#pragma unroll
                    for (int j = 0; j < K1_RPW; j++)
                        x1[j] = __ldcs((const u64*)(X + ro[j] + nb + 64));
                } else {
                    int nb = (kk - 6) * 128;
#pragma unroll
                    for (int j = 0; j < K1_RPW; j++)
                        x1[j] = __ldcs((const u64*)(X + ro_next[j] + nb + 64));
                }
#pragma unroll
                for (int p = 0; p < NP; p++) {
                    ulonglong2 qb = *(const ulonglong2*)&s_qp[p * C_DIM + cb + 64];
#pragma unroll
                    for (int j = 0; j < K1_RPW; j++) {
                        acc[j][p] = f2fma(xd[2 * j], qb.x, acc[j][p]);
                        acc[j][p] = f2fma(xd[2 * j + 1], qb.y, acc[j][p]);
                    }
                }
            }
        }

        u64 nmA = fpack(f2sum(nacc[0]), f2sum(nacc[2]));
        u64 nmB = fpack(f2sum(nacc[1]), f2sum(nacc[3]));

        u64 A[NP], Bv[NP];
#pragma unroll
        for (int p = 0; p < NP; p++) {
            u64 keepA = hi16 ? acc[1][p] : acc[0][p];
            u64 sendA = hi16 ? acc[0][p] : acc[1][p];
            A[p] = f2add(keepA, shfl_xor64(sendA, 16));
            u64 keepB = hi16 ? acc[3][p] : acc[2][p];
            u64 sendB = hi16 ? acc[2][p] : acc[3][p];
            Bv[p] = f2add(keepB, shfl_xor64(sendB, 16));
        }
        u64 keepN = hi16 ? nmB : nmA;
        u64 sendN = hi16 ? nmA : nmB;
        u64 nm = f2add(keepN, shfl_xor64(sendN, 16));

#pragma unroll
        for (int off = 8; off; off >>= 1) {
            nm = f2add(nm, shfl_xor64(nm, off));
#pragma unroll
            for (int p = 0; p < NP; p++) {
                A[p] = f2add(A[p], shfl_xor64(A[p], off));
                Bv[p] = f2add(Bv[p], shfl_xor64(Bv[p], off));
            }
        }

        // half-warp holds rows rA = row0 + (hi16?1:0), rB = rA + 2
        int rA = row0 + (hi16 ? 1 : 0);
        int rB = rA + 2;
        float scA = 100.0f / fmaxf(sqrtf(f2lo(nm)), 1e-12f);
        float scB = 100.0f / fmaxf(sqrtf(f2hi(nm)), 1e-12f);
        bool vA = (rA < N), vB = (rB < N);

        // logit stores (lanes 0 and 16)
        if (lane == 0 || lane == 16) {
#pragma unroll
            for (int p = 0; p < NP; p++) {
                float a0 = f2lo(A[p]) * scA, a1 = f2hi(A[p]) * scA;
                float b0 = f2lo(Bv[p]) * scB, b1 = f2hi(Bv[p]) * scB;
                if (vA) {
                    g_logits[(size_t)(2 * p) * N + rA] = a0;
                    g_logits[(size_t)(2 * p + 1) * N + rA] = a1;
                }
                if (vB) {
                    g_logits[(size_t)(2 * p) * N + rB] = b0;
                    g_logits[(size_t)(2 * p + 1) * N + rB] = b1;
                }
            }
        }

        // fused online (m,z): lane lq<NQ of each half owns query lq
        if (lq < NQ && (vA || vB)) {
            int p = lq >> 1;
            u64 va = A[p], vb = Bv[p];
            float lA = ((lq & 1) ? f2hi(va) : f2lo(va)) * scA;
            float lB = ((lq & 1) ? f2hi(vb) : f2lo(vb)) * scB;
            if (!vA) lA = -1e30f;
            if (!vB) lB = -1e30f;
            float2 mz = s_mz[warp][hi16 ? 1 : 0][lq];
            float mnew = fmaxf(mz.x, fmaxf(lA, lB));
            float z = mz.y;
            if (mnew > mz.x) z *= __expf(mz.x - mnew);
            z += __expf(lA - mnew) + __expf(lB - mnew);
            s_mz[warp][hi16 ? 1 : 0][lq] = make_float2(mnew, z);
        }

#pragma unroll
        for (int j = 0; j < K1_RPW; j++) ro[j] = ro_next[j];
    }

    __syncthreads();
    // block merge: thread t<NQ folds 16 (m,z) pairs for its q
    if (t < NQ) {
        float M = -1e30f;
#pragma unroll
        for (int w = 0; w < K1_WARPS; w++) {
            M = fmaxf(M, s_mz[w][0][t].x);
            M = fmaxf(M, s_mz[w][1][t].x);
        }
        float Z = 0.f;
#pragma unroll
        for (int w = 0; w < K1_WARPS; w++) {
            float2 a = s_mz[w][0][t], b = s_mz[w][1][t];
            Z += a.y * __expf(a.x - M) + b.y * __expf(b.x - M);
        }
        g_bmz[(size_t)blockIdx.x * NQ + t] = make_float2(M, Z);
    }
}

// ============================================================
// K1.5: final (M, Z) per q from per-block partials (grid = NQ)
// ============================================================
__global__ void k15_final(int nblocks) {
    int q = blockIdx.x;
    int t = threadIdx.x;   // 128
    __shared__ float red[128];

    float m = -1e30f;
    for (int b = t; b < nblocks; b += 128)
        m = fmaxf(m, g_bmz[(size_t)b * NQ + q].x);
    red[t] = m;
    __syncthreads();
    for (int s = 64; s > 0; s >>= 1) {
        if (t < s) red[t] = fmaxf(red[t], red[t + s]);
        __syncthreads();
    }
    float M = red[0];
    __syncthreads();

    float z = 0.f;
    for (int b = t; b < nblocks; b += 128) {
        float2 v = g_bmz[(size_t)b * NQ + q];
        z += v.y * __expf(v.x - M);
    }
    red[t] = z;
    __syncthreads();
    for (int s = 64; s > 0; s >>= 1) {
        if (t < s) red[t] += red[t + s];
        __syncthreads();
    }
    if (t == 0) { g_M[q] = M; g_Z[q] = red[0]; }
}

// ============================================================
// K2: balanced contiguous row range per block; chunked s_g gather;
// epilogue atomicAdds partials straight into g_pooled.
// ============================================================
__global__ __launch_bounds__(256) void k2_wsum(const float* __restrict__ X, int N) {
    __shared__ float s_g[K2_TILE];
    __shared__ float s_m[NQ], s_iz[NQ];
    int t = threadIdx.x;
    if (t < NQ) { s_m[t] = g_M[t]; s_iz[t] = (1.0f / NQ) / g_Z[t]; }
    __syncthreads();

    int r0 = (int)((long long)blockIdx.x * N / gridDim.x);
    int r1 = (int)((long long)(blockIdx.x + 1) * N / gridDim.x);

    float4 a = make_float4(0.f, 0.f, 0.f, 0.f);

    for (int n0 = r0; n0 < r1; n0 += K2_TILE) {
        int nv = min(K2_TILE, r1 - n0);
        __syncthreads();
        if (t < nv) {
            int n = n0 + t;
            float gs = 0.f;
#pragma unroll
            for (int q = 0; q < NQ; q++)
                gs = fmaf(__expf(g_logits[(size_t)q * N + n] - s_m[q]), s_iz[q], gs);
            s_g[t] = gs;
        }
        __syncthreads();

        const float* xb = X + (size_t)n0 * C_DIM + 4 * t;
        int r = 0;
        for (; r + 8 <= nv; r += 8) {
            float4 x[8];
#pragma unroll
            for (int i = 0; i < 8; i++)
                x[i] = __ldcs((const float4*)(xb + (size_t)(r + i) * C_DIM));
#pragma unroll
            for (int i = 0; i < 8; i++) {
                float g = s_g[r + i];
                a.x = fmaf(g, x[i].x, a.x); a.y = fmaf(g, x[i].y, a.y);
                a.z = fmaf(g, x[i].z, a.z); a.w = fmaf(g, x[i].w, a.w);
            }
        }
        for (; r < nv; r++) {
            float4 x = __ldcs((const float4*)(xb + (size_t)r * C_DIM));
            float g = s_g[r];
            a.x = fmaf(g, x.x, a.x); a.y = fmaf(g, x.y, a.y);
            a.z = fmaf(g, x.z, a.z); a.w = fmaf(g, x.w, a.w);
        }
    }
    atomicAdd(&g_pooled[4 * t + 0], a.x);
    atomicAdd(&g_pooled[4 * t + 1], a.y);
    atomicAdd(&g_pooled[4 * t + 2], a.z);
    atomicAdd(&g_pooled[4 * t + 3], a.w);
}

// ============================================================
// K3: out[j] = b[j] + sum_c pooled[c]*W[j][c]   (grid 128 x 256)
// ============================================================
__global__ __launch_bounds__(256) void k3_linear(const float* __restrict__ W,
                                                 const float* __restrict__ bias,
                                                 float* __restrict__ out) {
    int t = threadIdx.x;
    int j0 = blockIdx.x * 8;
    float4 p = *(const float4*)(g_pooled + 4 * t);
    float part[8];
#pragma unroll
    for (int j = 0; j < 8; j++) {
        const float4 w = *(const float4*)(W + (size_t)(j0 + j) * C_DIM + 4 * t);
        part[j] = fmaf(p.x, w.x, fmaf(p.y, w.y, fmaf(p.z, w.z, p.w * w.w)));
    }
#pragma unroll
    for (int j = 0; j < 8; j++)
#pragma unroll
        for (int off = 16; off; off >>= 1)
            part[j] += __shfl_xor_sync(0xffffffffu, part[j], off);
    __shared__ float s_p[8][8];
    int warp = t >> 5, lane = t & 31;
    if (lane == 0)
#pragma unroll
        for (int j = 0; j < 8; j++) s_p[warp][j] = part[j];
    __syncthreads();
    if (t < 8) {
        float s = 0.f;
#pragma unroll
        for (int w = 0; w < 8; w++) s += s_p[w][t];
        out[j0 + t] = s + bias[j0 + t];
    }
}

// ============================================================
extern "C" void kernel_launch(void* const* d_in, const int* in_sizes, int n_in,
                              void* d_out, int out_size) {
    const float* X = (const float*)d_in[0];
    const float* Q = (const float*)d_in[1];
    const float* W = (const float*)d_in[2];
    const float* b = (const float*)d_in[3];
    float* out = (float*)d_out;

    int N = in_sizes[0] / C_DIM;
    if (N > MAXN) N = MAXN;

    int k1_tiles = (N + K1_RPB - 1) / K1_RPB;
    int k1_grid = (K1_GRID < k1_tiles) ? K1_GRID : k1_tiles;
    int k2_grid = (K2_GRID < N) ? K2_GRID : N;

    k0a_norms<<<NQ + 1, 128>>>(Q);
    k0b_qp<<<8, 128>>>(Q);
    k1_logits<<<k1_grid, 256>>>(X, N, k1_tiles);
    k15_final<<<NQ, 128>>>(k1_grid);
    k2_wsum<<<k2_grid, 256>>>(X, N);
    k3_linear<<<128, 256>>>(W, b, out);
}